// round 2
// baseline (speedup 1.0000x reference)
#include <cuda_runtime.h>
#include <cstdint>
#include <cstddef>

#define CC   64      // number of HMM states (fixed by problem)
#define TPB  256     // 4 threads per state
#define LOG2E_F 1.4426950408889634f
#define LN2_F   0.6931471805599453f
#define LNPI2_F 1.8378770664093453f   // ln(2*pi)
#define HALF_LN2PI_F 0.91893853320467267f  // f32(0.5*ln(2pi)) — matches XLA const fold

__device__ __forceinline__ float ex2f(float x){ float r; asm("ex2.approx.ftz.f32 %0, %1;" : "=f"(r) : "f"(x)); return r; }
__device__ __forceinline__ float lg2f(float x){ float r; asm("lg2.approx.ftz.f32 %0, %1;" : "=f"(r) : "f"(x)); return r; }

extern __shared__ unsigned char smem_raw[];

__global__ __launch_bounds__(TPB, 1)
void hmm_fv_kernel(const float* __restrict__ x,
                   const float* __restrict__ om,
                   const float* __restrict__ os,
                   const float* __restrict__ logA,
                   const float* __restrict__ logpi,
                   float* __restrict__ out,
                   int B, int T)
{
    // ---- shared layout ----
    float* pS   = (float*)smem_raw;          // 64 floats: forward P_{t-1} (linear, normalized)
    float* dS   = pS + CC;                   // 64 floats: viterbi d_{t-1} (ln domain, UNNORMALIZED)
    float* smax = dS + CC;                   // 16 floats (8 used): per-warp maxima
    unsigned char* cbuf = (unsigned char*)(smax + 16);          // T bytes (padded)
    unsigned char* psiS = cbuf + ((T + 15) & ~15);              // T*CC bytes
    // preamble staging inside the psi region (psi written only at t>=1, after constants read)
    float* stage = (float*)psiS;             // CC*CC floats: raw logA
    float* rowM  = stage + CC*CC;            // CC floats: per-row max
    float* rowL  = rowM + CC;                // CC floats: per-row log(sum exp(shifted))

    const int tid = threadIdx.x;
    const int b   = blockIdx.x;
    const int c   = tid >> 2;     // state handled by this quad
    const int q   = tid & 3;      // slice within quad (16 predecessors each)

    // ================= preamble =================
    for (int idx = tid; idx < CC*CC; idx += TPB) stage[idx] = logA[idx];
    if (tid < CC) pS[tid] = logpi[tid];
    __syncthreads();

    // per-row max + log-sum-exp (sequential order, mirrors XLA row reduce)
    if (tid < CC) {
        const float* row = stage + tid*CC;
        float m = row[0];
        for (int j = 1; j < CC; j++) m = fmaxf(m, row[j]);
        float s = 0.f;
        for (int j = 0; j < CC; j++) s = __fadd_rn(s, expf(__fsub_rn(row[j], m)));
        rowM[tid] = m;
        rowL[tid] = logf(s);
    }
    __syncthreads();

    // per-thread transition constants: predecessors i = q*16 + j -> state c
    // LAln = log_softmax(logA, axis=1)[i][c]  (ref-exact op order)
    float LAln[16], Ac[16];
    #pragma unroll
    for (int j = 0; j < 16; j++) {
        int gi = q*16 + j;
        float sh = __fsub_rn(stage[gi*CC + c], rowM[gi]);
        float la = __fsub_rn(sh, rowL[gi]);
        LAln[j] = la;
        Ac[j]   = expf(la);          // forward-path probability (loose tolerance)
    }

    // normalized log pi (ln, ref-exact) and its log2 version for forward
    float lpiln, lpi2;
    {
        float m = pS[0];
        for (int j = 1; j < CC; j++) m = fmaxf(m, pS[j]);
        float s = 0.f;
        for (int j = 0; j < CC; j++) s = __fadd_rn(s, expf(__fsub_rn(pS[j], m)));
        float lse = logf(s);
        lpiln = __fsub_rn(__fsub_rn(pS[c], m), lse);
        lpi2  = lpiln * LOG2E_F;
    }

    // emission constants
    // ref-exact (Viterbi): mu, sigma, log(sigma)
    float mu[4], sg[4], lsg[4];
    // fused fast form (forward, log2): lp2 = K - sum (x*ea+eb)^2
    float ea[4], eb[4], K;
    {
        const float r = 0.84932180028801905f;     // sqrt(0.5 * log2(e))
        float k = -2.0f * LNPI2_F * LOG2E_F;
        #pragma unroll
        for (int d2 = 0; d2 < 4; d2++) {
            float mm = om[c*6 + d2];
            float sd = fmaxf(os[c*6 + d2], 0.f) + 0.1f;
            mu[d2] = mm; sg[d2] = sd; lsg[d2] = logf(sd);
            float a = r / sd;
            ea[d2] = a;
            eb[d2] = -mm * a;
            k -= lg2f(sd);
        }
        K = k;
    }
    __syncthreads();   // done with stage/rowM/rowL before psi overwrites them

    const float* xb = x + (size_t)b * (size_t)T * 6;
    float M2 = 0.f;

    float2 xA = *(const float2*)(xb);
    float2 xB = *(const float2*)(xb + 2);

    // ref-exact ln-domain emission logprob for current x regs, state c
    auto emit_ln = [&](float x0, float x1, float x2, float x3) -> float {
        float z0 = __fdiv_rn(__fsub_rn(x0, mu[0]), sg[0]);
        float z1 = __fdiv_rn(__fsub_rn(x1, mu[1]), sg[1]);
        float z2 = __fdiv_rn(__fsub_rn(x2, mu[2]), sg[2]);
        float z3 = __fdiv_rn(__fsub_rn(x3, mu[3]), sg[3]);
        float t0 = __fsub_rn(__fsub_rn(__fmul_rn(__fmul_rn(-0.5f, z0), z0), lsg[0]), HALF_LN2PI_F);
        float t1 = __fsub_rn(__fsub_rn(__fmul_rn(__fmul_rn(-0.5f, z1), z1), lsg[1]), HALF_LN2PI_F);
        float t2 = __fsub_rn(__fsub_rn(__fmul_rn(__fmul_rn(-0.5f, z2), z2), lsg[2]), HALF_LN2PI_F);
        float t3 = __fsub_rn(__fsub_rn(__fmul_rn(__fmul_rn(-0.5f, z3), z3), lsg[3]), HALF_LN2PI_F);
        return __fadd_rn(__fadd_rn(__fadd_rn(t0, t1), t2), t3);
    };

    // ---- t = 0 ----
    {
        // forward (fast log2)
        float y0 = fmaf(xA.x, ea[0], eb[0]);
        float y1 = fmaf(xA.y, ea[1], eb[1]);
        float y2 = fmaf(xB.x, ea[2], eb[2]);
        float y3 = fmaf(xB.y, ea[3], eb[3]);
        float lp2 = K - fmaf(y0,y0, fmaf(y1,y1, fmaf(y2,y2, y3*y3)));
        float a2 = lp2 + lpi2;

        // viterbi (ref-exact ln)
        float lpln = emit_ln(xA.x, xA.y, xB.x, xB.y);
        float d0 = __fadd_rn(lpln, lpiln);

        float wm = a2;
        wm = fmaxf(wm, __shfl_xor_sync(0xFFFFFFFFu, wm, 4));
        wm = fmaxf(wm, __shfl_xor_sync(0xFFFFFFFFu, wm, 8));
        wm = fmaxf(wm, __shfl_xor_sync(0xFFFFFFFFu, wm, 16));
        if ((tid & 31) == 0) smax[tid >> 5] = wm;
        __syncthreads();
        float m2 = fmaxf(fmaxf(fmaxf(smax[0],smax[1]),fmaxf(smax[2],smax[3])),
                         fmaxf(fmaxf(smax[4],smax[5]),fmaxf(smax[6],smax[7])));
        M2 = m2;
        if (q == 0) { pS[c] = ex2f(a2 - m2); dS[c] = d0; }
        __syncthreads();
    }

    if (T > 1) {
        xA = *(const float2*)(xb + 6);
        xB = *(const float2*)(xb + 8);
    }

    // ---- main loop ----
    for (int t = 1; t < T; t++) {
        // prefetch x[t+1]
        int tn = (t + 1 < T) ? (t + 1) : t;
        float2 nA = *(const float2*)(xb + (size_t)tn*6);
        float2 nB = *(const float2*)(xb + (size_t)tn*6 + 2);

        // forward emission (fast log2)
        float y0 = fmaf(xA.x, ea[0], eb[0]);
        float y1 = fmaf(xA.y, ea[1], eb[1]);
        float y2 = fmaf(xB.x, ea[2], eb[2]);
        float y3 = fmaf(xB.y, ea[3], eb[3]);
        float lp2 = K - fmaf(y0,y0, fmaf(y1,y1, fmaf(y2,y2, y3*y3)));

        // viterbi emission (ref-exact ln)
        float lpln = emit_ln(xA.x, xA.y, xB.x, xB.y);

        const float4* p4 = (const float4*)pS + q*4;
        const float4* d4 = (const float4*)dS + q*4;
        float dot0 = 0.f, dot1 = 0.f, dot2 = 0.f, dot3 = 0.f;
        float best = -3.4e38f; int barg = 0;
        #pragma unroll
        for (int j = 0; j < 4; j++) {
            float4 pv = p4[j];
            dot0 = fmaf(pv.x, Ac[j*4+0], dot0);
            dot1 = fmaf(pv.y, Ac[j*4+1], dot1);
            dot2 = fmaf(pv.z, Ac[j*4+2], dot2);
            dot3 = fmaf(pv.w, Ac[j*4+3], dot3);
            float4 dv = d4[j];
            float w;
            // ref-exact single adds; first-max-wins (ascending i)
            w = __fadd_rn(dv.x, LAln[j*4+0]); if (w > best) { best = w; barg = j*4+0; }
            w = __fadd_rn(dv.y, LAln[j*4+1]); if (w > best) { best = w; barg = j*4+1; }
            w = __fadd_rn(dv.z, LAln[j*4+2]); if (w > best) { best = w; barg = j*4+2; }
            w = __fadd_rn(dv.w, LAln[j*4+3]); if (w > best) { best = w; barg = j*4+3; }
        }
        float dot = (dot0 + dot1) + (dot2 + dot3);
        barg += q * 16;

        // quad reduce (lanes 4c..4c+3 in same warp); lower index wins ties
        #pragma unroll
        for (int off = 1; off <= 2; off <<= 1) {
            dot += __shfl_xor_sync(0xFFFFFFFFu, dot, off);
            float wb = __shfl_xor_sync(0xFFFFFFFFu, best, off);
            int   ib = __shfl_xor_sync(0xFFFFFFFFu, barg, off);
            if (wb > best || (wb == best && ib < barg)) { best = wb; barg = ib; }
        }

        float a2 = lp2 + lg2f(dot);

        // block max of a2 over states (forward scaler)
        float wm = a2;
        wm = fmaxf(wm, __shfl_xor_sync(0xFFFFFFFFu, wm, 4));
        wm = fmaxf(wm, __shfl_xor_sync(0xFFFFFFFFu, wm, 8));
        wm = fmaxf(wm, __shfl_xor_sync(0xFFFFFFFFu, wm, 16));
        if ((tid & 31) == 0) smax[tid >> 5] = wm;
        __syncthreads();
        float m2 = fmaxf(fmaxf(fmaxf(smax[0],smax[1]),fmaxf(smax[2],smax[3])),
                         fmaxf(fmaxf(smax[4],smax[5]),fmaxf(smax[6],smax[7])));
        M2 += m2;

        float Pn = ex2f(a2 - m2);
        float dn = __fadd_rn(best, lpln);   // ref-exact: max(scores) + lp_t, unnormalized
        if (q == 0) {
            pS[c] = Pn;
            dS[c] = dn;
            psiS[t*CC + c] = (unsigned char)barg;
        }
        __syncthreads();

        xA = nA; xB = nB;
    }

    // ---- finalize: logp_x, viterbi backtrack ----
    if (tid == 0) {
        float s = 0.f;
        for (int j = 0; j < CC; j++) s += pS[j];
        out[b] = LN2_F * (M2 + lg2f(s));

        float bd = dS[0]; int cl = 0;
        for (int j = 1; j < CC; j++) { float v = dS[j]; if (v > bd) { bd = v; cl = j; } }
        int cc = cl;
        cbuf[T-1] = (unsigned char)cc;
        for (int t = T - 1; t >= 1; t--) {
            cc = psiS[t*CC + cc];
            cbuf[t-1] = (unsigned char)cc;
        }
    }
    __syncthreads();

    float* outc = out + B;
    for (int idx = tid; idx < T; idx += TPB)
        outc[(size_t)b * T + idx] = (float)cbuf[idx];
}

extern "C" void kernel_launch(void* const* d_in, const int* in_sizes, int n_in,
                              void* d_out, int out_size)
{
    const float* x    = (const float*)d_in[0];
    const float* om   = (const float*)d_in[1];
    const float* os   = (const float*)d_in[2];
    const float* lA   = (const float*)d_in[3];
    const float* lpi  = (const float*)d_in[4];

    // out_size = B*(T+1), x elems = B*T*6  ->  B = out_size - x/6
    int B = out_size - in_sizes[0] / 6;
    int T = in_sizes[0] / (6 * B);

    size_t smemsz = (size_t)(CC + CC + 16) * sizeof(float)    // pS, dS, smax
                  + (size_t)((T + 15) & ~15)                  // cbuf
                  + (size_t)T * CC;                           // psi
    cudaFuncSetAttribute(hmm_fv_kernel,
                         cudaFuncAttributeMaxDynamicSharedMemorySize,
                         (int)smemsz);

    hmm_fv_kernel<<<B, TPB, smemsz>>>(x, om, os, lA, lpi, (float*)d_out, B, T);
}

// round 6
// speedup vs baseline: 1.0356x; 1.0356x over previous
#include <cuda_runtime.h>
#include <cstdint>
#include <cstddef>

#define CC   64      // number of HMM states
#define TPB  256     // 4 threads (quad) per state
#define LOG2E_F 1.4426950408889634f
#define LN2_F   0.6931471805599453f
#define LNPI2_F 1.8378770664093453f        // ln(2*pi)
#define HALF_LN2PI_F 0.91893853320467267f  // f32(0.5*ln(2pi))

__device__ __forceinline__ float ex2f(float x){ float r; asm("ex2.approx.ftz.f32 %0, %1;" : "=f"(r) : "f"(x)); return r; }
__device__ __forceinline__ float lg2f(float x){ float r; asm("lg2.approx.ftz.f32 %0, %1;" : "=f"(r) : "f"(x)); return r; }

extern __shared__ unsigned char smem_raw[];

__global__ __launch_bounds__(TPB, 1)
void hmm_fv_kernel(const float* __restrict__ x,
                   const float* __restrict__ om,
                   const float* __restrict__ os,
                   const float* __restrict__ logA,
                   const float* __restrict__ logpi,
                   float* __restrict__ out,
                   int B, int T)
{
    // ---- shared layout (all float regions 16B aligned) ----
    float* fbase = (float*)smem_raw;
    float* pS0 = fbase;            // 64: forward P (buf 0), per-warp normalized
    float* pS1 = fbase + 64;       // 64
    float* dS0 = fbase + 128;      // 64: viterbi d (ln domain, unnormalized)
    float* dS1 = fbase + 192;      // 64
    float* sx0 = fbase + 256;      // 8: per-warp a2 maxima (buf 0)
    float* sx1 = fbase + 264;      // 8
    unsigned char* cbuf = (unsigned char*)(fbase + 272);        // T bytes (padded)
    unsigned char* psiS = cbuf + ((T + 15) & ~15);              // T*CC bytes
    // preamble staging inside psi region (psi rows written only at t>=1, after constants read)
    float* stage = (float*)psiS;             // CC*CC: raw logA
    float* rowM  = stage + CC*CC;            // CC: row max
    float* rowL  = rowM + CC;                // CC: row log-sum-exp

    const int tid = threadIdx.x;
    const int b   = blockIdx.x;
    const int c   = tid >> 2;     // state
    const int q   = tid & 3;      // quad slice: 16 predecessors + emission dim q

    // ================= preamble =================
    for (int idx = tid; idx < CC*CC; idx += TPB) stage[idx] = logA[idx];
    if (tid < CC) pS0[tid] = logpi[tid];
    __syncthreads();

    if (tid < CC) {   // ref-exact row log-softmax pieces
        const float* row = stage + tid*CC;
        float m = row[0];
        for (int j = 1; j < CC; j++) m = fmaxf(m, row[j]);
        float s = 0.f;
        for (int j = 0; j < CC; j++) s = __fadd_rn(s, expf(__fsub_rn(row[j], m)));
        rowM[tid] = m;
        rowL[tid] = logf(s);
    }
    __syncthreads();

    // transition constants: predecessors i = q*16 + j -> state c
    float LAln[16], Ac[16];
    #pragma unroll
    for (int j = 0; j < 16; j++) {
        int gi = q*16 + j;
        float la = __fsub_rn(__fsub_rn(stage[gi*CC + c], rowM[gi]), rowL[gi]);
        LAln[j] = la;
        Ac[j]   = expf(la);
    }

    // normalized log pi (ref-exact ln) + log2 version
    float lpiln, lpi2;
    {
        float m = pS0[0];
        for (int j = 1; j < CC; j++) m = fmaxf(m, pS0[j]);
        float s = 0.f;
        for (int j = 0; j < CC; j++) s = __fadd_rn(s, expf(__fsub_rn(pS0[j], m)));
        float lse = logf(s);
        lpiln = __fsub_rn(__fsub_rn(pS0[c], m), lse);
        lpi2  = lpiln * LOG2E_F;
    }

    // per-lane emission constants (dim q of state c)
    float muq = om[c*6 + q];
    float sgq = fmaxf(os[c*6 + q], 0.f) + 0.1f;
    float lsgq = logf(sgq);                        // ref-exact log(sigma)
    const float rconst = 0.84932180028801905f;     // sqrt(0.5*log2 e)
    float eaq = rconst / sgq;
    float ebq = -muq * eaq;
    float K;
    {   // K = -4*0.5*ln(2pi)*log2e - sum_d log2(sd)   (forward, loose)
        float kp = lg2f(sgq);
        kp += __shfl_xor_sync(0xFFFFFFFFu, kp, 1);
        kp += __shfl_xor_sync(0xFFFFFFFFu, kp, 2);
        K = -2.0f * LNPI2_F * LOG2E_F - kp;
    }
    __syncthreads();   // readers of stage/rowM/rowL/pS0 done before overwrite

    const float* xb = x + (size_t)b * (size_t)T * 6;
    float M2 = 0.f;    // accumulates global shifts; first addition at t=1

    // ---- t = 0: per-warp normalized init, ONE bar ----
    {
        float xq = __ldg(xb + q);
        float z  = __fdiv_rn(__fsub_rn(xq, muq), sgq);
        float tq = __fsub_rn(__fsub_rn(__fmul_rn(__fmul_rn(-0.5f, z), z), lsgq), HALF_LN2PI_F);
        float yq = fmaf(xq, eaq, ebq);
        float y2 = yq * yq;

        float b1 = __shfl_xor_sync(0xFFFFFFFFu, tq, 1);
        float c2 = __shfl_xor_sync(0xFFFFFFFFu, tq, 2);
        float c3 = __shfl_xor_sync(0xFFFFFFFFu, b1, 2);
        float lpln = __fadd_rn(__fadd_rn(__fadd_rn(tq, b1), c2), c3);  // ref order on q==0

        float sy2 = y2 + __shfl_xor_sync(0xFFFFFFFFu, y2, 1);
        sy2 += __shfl_xor_sync(0xFFFFFFFFu, sy2, 2);
        float lp2 = K - sy2;

        float a2 = lp2 + lpi2;
        float d0 = __fadd_rn(lpln, lpiln);   // ref: logp + log_pi

        // warp max of a2 (8 states per warp; a2 is quad-uniform)
        float wm = a2;
        wm = fmaxf(wm, __shfl_xor_sync(0xFFFFFFFFu, wm, 4));
        wm = fmaxf(wm, __shfl_xor_sync(0xFFFFFFFFu, wm, 8));
        wm = fmaxf(wm, __shfl_xor_sync(0xFFFFFFFFu, wm, 16));

        if ((tid & 31) == 0) sx0[tid >> 5] = wm;
        if (q == 0) { pS0[c] = ex2f(a2 - wm); dS0[c] = d0; }   // per-warp normalized
        __syncthreads();
    }

    // ---- main loop: ONE __syncthreads per step, double-buffered ----
    float *pR = pS0, *pW = pS1, *dR = dS0, *dW = dS1, *sxR = sx0, *sxW = sx1;
    unsigned char* psp = psiS + CC;
    const float* xp = xb + 6 + q;
    float xq = __ldg(xp);

    for (int t = 1; t < T; t++) {
        // prefetch x for t+1 (clamped)
        const float* xpn = (t + 1 < T) ? (xp + 6) : xp;
        float xqn = __ldg(xpn);

        // previous step's per-warp maxima -> global max m2 + this lane's 2 group factors
        float4 s0 = *(const float4*)sxR, s1 = *((const float4*)sxR + 1);
        float m2 = fmaxf(fmaxf(fmaxf(s0.x,s0.y),fmaxf(s0.z,s0.w)),
                         fmaxf(fmaxf(s1.x,s1.y),fmaxf(s1.z,s1.w)));
        M2 += m2;
        float wa, wb;   // maxima of source warps 2q and 2q+1
        if      (q == 0) { wa = s0.x; wb = s0.y; }
        else if (q == 1) { wa = s0.z; wb = s0.w; }
        else if (q == 2) { wa = s1.x; wb = s1.y; }
        else             { wa = s1.z; wb = s1.w; }
        float fA = ex2f(wa - m2);
        float fB = ex2f(wb - m2);

        // emission (per-lane, 1 div)
        float z  = __fdiv_rn(__fsub_rn(xq, muq), sgq);
        float tq = __fsub_rn(__fsub_rn(__fmul_rn(__fmul_rn(-0.5f, z), z), lsgq), HALF_LN2PI_F);
        float yq = fmaf(xq, eaq, ebq);
        float y2 = yq * yq;

        float bb1 = __shfl_xor_sync(0xFFFFFFFFu, tq, 1);
        float cc2 = __shfl_xor_sync(0xFFFFFFFFu, tq, 2);
        float cc3 = __shfl_xor_sync(0xFFFFFFFFu, bb1, 2);
        float lpln = __fadd_rn(__fadd_rn(__fadd_rn(tq, bb1), cc2), cc3);  // ref-order on q==0

        float sy2 = y2 + __shfl_xor_sync(0xFFFFFFFFu, y2, 1);
        sy2 += __shfl_xor_sync(0xFFFFFFFFu, sy2, 2);
        float lp2 = K - sy2;

        // forward dot (split by source warp) + viterbi max-plus over 16 predecessors
        const float4* p4 = (const float4*)pR + q*4;
        const float4* d4 = (const float4*)dR + q*4;
        float dA0 = 0.f, dA1 = 0.f, dB0 = 0.f, dB1 = 0.f;
        float best = -3.4e38f; int barg = 0;
        #pragma unroll
        for (int j = 0; j < 2; j++) {        // predecessors from warp 2q
            float4 pv = p4[j];
            dA0 = fmaf(pv.x, Ac[j*4+0], dA0);
            dA1 = fmaf(pv.y, Ac[j*4+1], dA1);
            dA0 = fmaf(pv.z, Ac[j*4+2], dA0);
            dA1 = fmaf(pv.w, Ac[j*4+3], dA1);
            float4 dv = d4[j];
            float w;
            w = __fadd_rn(dv.x, LAln[j*4+0]); if (w > best) { best = w; barg = j*4+0; }
            w = __fadd_rn(dv.y, LAln[j*4+1]); if (w > best) { best = w; barg = j*4+1; }
            w = __fadd_rn(dv.z, LAln[j*4+2]); if (w > best) { best = w; barg = j*4+2; }
            w = __fadd_rn(dv.w, LAln[j*4+3]); if (w > best) { best = w; barg = j*4+3; }
        }
        #pragma unroll
        for (int j = 2; j < 4; j++) {        // predecessors from warp 2q+1
            float4 pv = p4[j];
            dB0 = fmaf(pv.x, Ac[j*4+0], dB0);
            dB1 = fmaf(pv.y, Ac[j*4+1], dB1);
            dB0 = fmaf(pv.z, Ac[j*4+2], dB0);
            dB1 = fmaf(pv.w, Ac[j*4+3], dB1);
            float4 dv = d4[j];
            float w;
            w = __fadd_rn(dv.x, LAln[j*4+0]); if (w > best) { best = w; barg = j*4+0; }
            w = __fadd_rn(dv.y, LAln[j*4+1]); if (w > best) { best = w; barg = j*4+1; }
            w = __fadd_rn(dv.z, LAln[j*4+2]); if (w > best) { best = w; barg = j*4+2; }
            w = __fadd_rn(dv.w, LAln[j*4+3]); if (w > best) { best = w; barg = j*4+3; }
        }
        float dot = fmaf(fA, dA0 + dA1, fB * (dB0 + dB1));
        barg += q * 16;

        #pragma unroll
        for (int off = 1; off <= 2; off <<= 1) {
            dot += __shfl_xor_sync(0xFFFFFFFFu, dot, off);
            float wbx = __shfl_xor_sync(0xFFFFFFFFu, best, off);
            int   ibx = __shfl_xor_sync(0xFFFFFFFFu, barg, off);
            if (wbx > best || (wbx == best && ibx < barg)) { best = wbx; barg = ibx; }
        }

        float a2 = lp2 + lg2f(dot);

        // warp max of a2 (local, no bar needed)
        float wm = a2;
        wm = fmaxf(wm, __shfl_xor_sync(0xFFFFFFFFu, wm, 4));
        wm = fmaxf(wm, __shfl_xor_sync(0xFFFFFFFFu, wm, 8));
        wm = fmaxf(wm, __shfl_xor_sync(0xFFFFFFFFu, wm, 16));

        float Pn = ex2f(a2 - wm);            // per-warp normalization: never all-flush
        float dn = __fadd_rn(best, lpln);    // ref-exact, unnormalized

        if ((tid & 31) == 0) sxW[tid >> 5] = wm;
        if (q == 0) {
            pW[c] = Pn;
            dW[c] = dn;
            psp[c] = (unsigned char)barg;
        }
        psp += CC; xq = xqn; xp = xpn;

        float* tf;
        tf = pR;  pR  = pW;  pW  = tf;
        tf = dR;  dR  = dW;  dW  = tf;
        tf = sxR; sxR = sxW; sxW = tf;

        __syncthreads();
    }

    // ---- finalize: logp_x + viterbi backtrack (last written = pR/dR/sxR) ----
    if (tid == 0) {
        float m2l = sxR[0];
        for (int w = 1; w < 8; w++) m2l = fmaxf(m2l, sxR[w]);
        float s = 0.f;
        for (int w = 0; w < 8; w++) {
            float sub = 0.f;
            for (int k = 0; k < 8; k++) sub += pR[w*8 + k];
            s += ex2f(sxR[w] - m2l) * sub;
        }
        out[b] = LN2_F * (M2 + m2l + lg2f(s));

        float bd = dR[0]; int cl = 0;
        for (int j = 1; j < CC; j++) { float v = dR[j]; if (v > bd) { bd = v; cl = j; } }
        int cc = cl;
        cbuf[T-1] = (unsigned char)cc;
        for (int t = T - 1; t >= 1; t--) {
            cc = psiS[t*CC + cc];
            cbuf[t-1] = (unsigned char)cc;
        }
    }
    __syncthreads();

    float* outc = out + B;
    for (int idx = tid; idx < T; idx += TPB)
        outc[(size_t)b * T + idx] = (float)cbuf[idx];
}

extern "C" void kernel_launch(void* const* d_in, const int* in_sizes, int n_in,
                              void* d_out, int out_size)
{
    const float* x    = (const float*)d_in[0];
    const float* om   = (const float*)d_in[1];
    const float* os   = (const float*)d_in[2];
    const float* lA   = (const float*)d_in[3];
    const float* lpi  = (const float*)d_in[4];

    int B = out_size - in_sizes[0] / 6;
    int T = in_sizes[0] / (6 * B);

    size_t smemsz = (size_t)272 * sizeof(float)        // pS0/1, dS0/1, sx0/1
                  + (size_t)((T + 15) & ~15)           // cbuf
                  + (size_t)T * CC;                    // psi
    size_t stage_need = (size_t)272 * sizeof(float) + (size_t)((T + 15) & ~15)
                      + (size_t)(CC*CC + 2*CC) * sizeof(float);
    if (stage_need > smemsz) smemsz = stage_need;

    cudaFuncSetAttribute(hmm_fv_kernel,
                         cudaFuncAttributeMaxDynamicSharedMemorySize,
                         (int)smemsz);

    hmm_fv_kernel<<<B, TPB, smemsz>>>(x, om, os, lA, lpi, (float*)d_out, B, T);
}